// round 11
// baseline (speedup 1.0000x reference)
#include <cuda_runtime.h>
#include <stdint.h>
#include <math.h>

#define NN 40000
#define MAXE 700000   // E (640k) + self loops (40k) with slack

// ---------------------------------------------------------------------------
// Scratch (device globals)
// ---------------------------------------------------------------------------
__device__ float g_xh1[NN * 256];   // x @ gat1_W
__device__ float g_acc1[NN * 256];  // GAT1 output
__device__ float g_as1[NN * 2];
__device__ float g_ad1[NN * 2];
__device__ float g_xh2[NN * 64];    // gat1out @ gat2_W
__device__ float g_as2[NN];
__device__ float g_ad2[NN];
__device__ float g_xw1[NN * 128];   // x @ gcn1_W
__device__ float g_gcn1[NN * 128];  // GCN1 output
__device__ float g_xw2[NN * 64];
__device__ float g_dinv[NN];
__device__ float g_cat[NN * 128];   // [gcn2*wc | gat2*wt]
__device__ float g_y1[NN * 256];
__device__ float g_y2[NN * 128];
// CSR scratch
__device__ int g_counts[NN];
__device__ int g_rs[NN + 1];
__device__ int g_cursor[NN];
__device__ int g_csr[MAXE];         // src ids grouped by dst

// ---------------------------------------------------------------------------
// CSR build
// ---------------------------------------------------------------------------
__global__ void zero_int_kernel(int* p, int n) {
    int i = blockIdx.x * blockDim.x + threadIdx.x;
    if (i < n) p[i] = 0;
}

__global__ void hist_kernel(const int* __restrict__ dst, int* __restrict__ counts,
                            int E, int Etot) {
    int t = blockIdx.x * blockDim.x + threadIdx.x;
    if (t >= Etot) return;
    int d = (t < E) ? dst[t] : (t - E);
    atomicAdd(&counts[d], 1);
}

// single-block exclusive scan of 40k counts -> rs (and cursor), rs[n] = total
__global__ void scan_kernel(const int* __restrict__ counts, int* __restrict__ rs,
                            int* __restrict__ cursor, int n) {
    __shared__ int sums[1024];
    int t = threadIdx.x;
    int per = (n + 1023) >> 10;
    int beg = t * per;
    int end = min(beg + per, n);
    int s = 0;
    for (int i = beg; i < end; i++) s += counts[i];
    sums[t] = s;
    __syncthreads();
    for (int off = 1; off < 1024; off <<= 1) {
        int v = (t >= off) ? sums[t - off] : 0;
        __syncthreads();
        sums[t] += v;
        __syncthreads();
    }
    int base = (t == 0) ? 0 : sums[t - 1];
    for (int i = beg; i < end; i++) {
        rs[i] = base;
        cursor[i] = base;
        base += counts[i];
    }
    if (beg < n && end == n) rs[n] = base;
}

__global__ void csr_fill_kernel(const int* __restrict__ src, const int* __restrict__ dst,
                                int* __restrict__ cursor, int* __restrict__ csr,
                                int E, int Etot) {
    int t = blockIdx.x * blockDim.x + threadIdx.x;
    if (t >= Etot) return;
    int s = (t < E) ? src[t] : (t - E);
    int d = (t < E) ? dst[t] : (t - E);
    int pos = atomicAdd(&cursor[d], 1);
    csr[pos] = s;
}

__global__ void dinv_kernel(const int* __restrict__ counts, float* __restrict__ dinv, int n) {
    int t = blockIdx.x * blockDim.x + threadIdx.x;
    if (t >= n) return;
    dinv[t] = rsqrtf(fmaxf((float)counts[t], 1.0f));
}

// ---------------------------------------------------------------------------
// TF32 tensor-core GEMM (identical to round 10)
// ---------------------------------------------------------------------------
__device__ __forceinline__ uint32_t f2tf(float x) {
    uint32_t r;
    asm("cvt.rna.tf32.f32 %0, %1;" : "=r"(r) : "f"(x));
    return r;
}

__device__ __forceinline__ void mma_tf32(float* c, const uint32_t* a, const uint32_t* b) {
    asm volatile(
        "mma.sync.aligned.m16n8k8.row.col.f32.tf32.tf32.f32 "
        "{%0,%1,%2,%3}, {%4,%5,%6,%7}, {%8,%9}, {%0,%1,%2,%3};"
        : "+f"(c[0]), "+f"(c[1]), "+f"(c[2]), "+f"(c[3])
        : "r"(a[0]), "r"(a[1]), "r"(a[2]), "r"(a[3]), "r"(b[0]), "r"(b[1]));
}

template <int BN>
__global__ __launch_bounds__(256) void gemm_tf32_kernel(
        const float* __restrict__ A, const float* __restrict__ B,
        const float* __restrict__ bias, float* __restrict__ C,
        int Nc, int K) {
    constexpr int WN = BN / 4;
    constexpr int NT = WN / 8;
    constexpr int NB4 = BN / 4;
    constexpr int BLD = (BN == 128) ? 4 : 2;
    __shared__ float As[64][36];
    __shared__ float Bs[32][BN + 8];

    const int t = threadIdx.x;
    const int lane = t & 31;
    const int w = t >> 5;
    const int wm = w & 1;
    const int wn = w >> 1;
    const int row0 = blockIdx.y * 64;
    const int col0 = blockIdx.x * BN;

    const int ar0 = t >> 3, acc4_0 = (t & 7) * 4;
    const int ar1 = (t + 256) >> 3, acc4_1 = acc4_0;

    float acc[2][NT][4];
#pragma unroll
    for (int mi = 0; mi < 2; mi++)
#pragma unroll
        for (int ni = 0; ni < NT; ni++)
#pragma unroll
            for (int q = 0; q < 4; q++) acc[mi][ni][q] = 0.0f;

    const int nch = K >> 5;

    float4 pa0, pa1, pb[BLD];
    pa0 = *(const float4*)&A[(size_t)(row0 + ar0) * K + acc4_0];
    pa1 = *(const float4*)&A[(size_t)(row0 + ar1) * K + acc4_1];
#pragma unroll
    for (int i = 0; i < BLD; i++) {
        int id = t + i * 256;
        int kr = id / NB4, c4 = (id % NB4) * 4;
        pb[i] = *(const float4*)&B[(size_t)kr * Nc + col0 + c4];
    }

    for (int ch = 0; ch < nch; ch++) {
        As[ar0][acc4_0 + 0] = __uint_as_float(f2tf(pa0.x));
        As[ar0][acc4_0 + 1] = __uint_as_float(f2tf(pa0.y));
        As[ar0][acc4_0 + 2] = __uint_as_float(f2tf(pa0.z));
        As[ar0][acc4_0 + 3] = __uint_as_float(f2tf(pa0.w));
        As[ar1][acc4_1 + 0] = __uint_as_float(f2tf(pa1.x));
        As[ar1][acc4_1 + 1] = __uint_as_float(f2tf(pa1.y));
        As[ar1][acc4_1 + 2] = __uint_as_float(f2tf(pa1.z));
        As[ar1][acc4_1 + 3] = __uint_as_float(f2tf(pa1.w));
#pragma unroll
        for (int i = 0; i < BLD; i++) {
            int id = t + i * 256;
            int kr = id / NB4, c4 = (id % NB4) * 4;
            Bs[kr][c4 + 0] = __uint_as_float(f2tf(pb[i].x));
            Bs[kr][c4 + 1] = __uint_as_float(f2tf(pb[i].y));
            Bs[kr][c4 + 2] = __uint_as_float(f2tf(pb[i].z));
            Bs[kr][c4 + 3] = __uint_as_float(f2tf(pb[i].w));
        }
        __syncthreads();

        if (ch + 1 < nch) {
            const int k0 = (ch + 1) << 5;
            pa0 = *(const float4*)&A[(size_t)(row0 + ar0) * K + k0 + acc4_0];
            pa1 = *(const float4*)&A[(size_t)(row0 + ar1) * K + k0 + acc4_1];
#pragma unroll
            for (int i = 0; i < BLD; i++) {
                int id = t + i * 256;
                int kr = id / NB4, c4 = (id % NB4) * 4;
                pb[i] = *(const float4*)&B[(size_t)(k0 + kr) * Nc + col0 + c4];
            }
        }

#pragma unroll
        for (int k8 = 0; k8 < 4; k8++) {
            const int kb = k8 * 8;
            uint32_t af[2][4];
#pragma unroll
            for (int mi = 0; mi < 2; mi++) {
                const int rb = wm * 32 + mi * 16 + (lane >> 2);
                const int cb = kb + (lane & 3);
                af[mi][0] = __float_as_uint(As[rb][cb]);
                af[mi][1] = __float_as_uint(As[rb + 8][cb]);
                af[mi][2] = __float_as_uint(As[rb][cb + 4]);
                af[mi][3] = __float_as_uint(As[rb + 8][cb + 4]);
            }
            uint32_t bf[NT][2];
#pragma unroll
            for (int ni = 0; ni < NT; ni++) {
                const int nb = wn * WN + ni * 8 + (lane >> 2);
                const int kk = kb + (lane & 3);
                bf[ni][0] = __float_as_uint(Bs[kk][nb]);
                bf[ni][1] = __float_as_uint(Bs[kk + 4][nb]);
            }
#pragma unroll
            for (int mi = 0; mi < 2; mi++)
#pragma unroll
                for (int ni = 0; ni < NT; ni++)
                    mma_tf32(acc[mi][ni], af[mi], bf[ni]);
        }
        __syncthreads();
    }

#pragma unroll
    for (int mi = 0; mi < 2; mi++) {
        const int rowa = row0 + wm * 32 + mi * 16 + (lane >> 2);
#pragma unroll
        for (int ni = 0; ni < NT; ni++) {
            const int col = col0 + wn * WN + ni * 8 + (lane & 3) * 2;
            float b0 = bias ? bias[col] : 0.0f;
            float b1 = bias ? bias[col + 1] : 0.0f;
            float2 s0, s1;
            s0.x = acc[mi][ni][0] + b0; s0.y = acc[mi][ni][1] + b1;
            s1.x = acc[mi][ni][2] + b0; s1.y = acc[mi][ni][3] + b1;
            *(float2*)&C[(size_t)rowa * Nc + col] = s0;
            *(float2*)&C[(size_t)(rowa + 8) * Nc + col] = s1;
        }
    }
}

// ---------------------------------------------------------------------------
// Attention logits: per 'row' of xh (row = node*heads + h)
// ---------------------------------------------------------------------------
__global__ void att_kernel(const float* __restrict__ xh, const float* __restrict__ a_src,
                           const float* __restrict__ a_dst, float* __restrict__ out_s,
                           float* __restrict__ out_d, int rows, int heads, int ch) {
    int w = (blockIdx.x * blockDim.x + threadIdx.x) >> 5;
    int lane = threadIdx.x & 31;
    if (w >= rows) return;
    const float* row = xh + (size_t)w * ch;
    const float* as = a_src + (size_t)(w % heads) * ch;
    const float* ad = a_dst + (size_t)(w % heads) * ch;
    float ss = 0.0f, dd = 0.0f;
    for (int c = lane; c < ch; c += 32) {
        float v = row[c];
        ss += v * as[c];
        dd += v * ad[c];
    }
#pragma unroll
    for (int o = 16; o; o >>= 1) {
        ss += __shfl_down_sync(0xFFFFFFFFu, ss, o);
        dd += __shfl_down_sync(0xFFFFFFFFu, dd, o);
    }
    if (lane == 0) { out_s[w] = ss; out_d[w] = dd; }
}

// ---------------------------------------------------------------------------
// GAT pull (heads=2, ch=128): warp per dst, edge loop unrolled x4 for MLP.
// ---------------------------------------------------------------------------
__global__ __launch_bounds__(256) void gat_pull_2_128(
        const int* __restrict__ rs, const int* __restrict__ csr,
        const float* __restrict__ as_, const float* __restrict__ ad_,
        const float* __restrict__ xh, const float* __restrict__ bias,
        float* __restrict__ out) {
    int d = (blockIdx.x * blockDim.x + threadIdx.x) >> 5;
    int lane = threadIdx.x & 31;
    if (d >= NN) return;
    int beg = rs[d], end = rs[d + 1];
    float ad0 = ad_[d * 2 + 0], ad1 = ad_[d * 2 + 1];
    // pass 1: max logit per head (lanes strided over edges)
    float m0 = -INFINITY, m1 = -INFINITY;
    for (int j = beg + lane; j < end; j += 32) {
        int s = __ldg(&csr[j]);
        float l0 = as_[s * 2 + 0] + ad0; l0 = l0 > 0.f ? l0 : 0.2f * l0;
        float l1 = as_[s * 2 + 1] + ad1; l1 = l1 > 0.f ? l1 : 0.2f * l1;
        m0 = fmaxf(m0, l0); m1 = fmaxf(m1, l1);
    }
#pragma unroll
    for (int o = 16; o; o >>= 1) {
        m0 = fmaxf(m0, __shfl_xor_sync(0xFFFFFFFFu, m0, o));
        m1 = fmaxf(m1, __shfl_xor_sync(0xFFFFFFFFu, m1, o));
    }
    // pass 2: exp-sum + weighted feature sum, unrolled x4
    float s0 = 0.f, s1 = 0.f;
    float f0[4] = {0.f, 0.f, 0.f, 0.f};
    float f1[4] = {0.f, 0.f, 0.f, 0.f};
    int j = beg;
    for (; j + 4 <= end; j += 4) {
        int sv[4];
#pragma unroll
        for (int u = 0; u < 4; u++) sv[u] = __ldg(&csr[j + u]);
        float a0[4], a1[4];
#pragma unroll
        for (int u = 0; u < 4; u++) {
            float l0 = as_[sv[u] * 2 + 0] + ad0; l0 = l0 > 0.f ? l0 : 0.2f * l0;
            float l1 = as_[sv[u] * 2 + 1] + ad1; l1 = l1 > 0.f ? l1 : 0.2f * l1;
            a0[u] = __expf(l0 - m0); a1[u] = __expf(l1 - m1);
        }
        float4 v0[4], v1[4];
#pragma unroll
        for (int u = 0; u < 4; u++) {
            const float4* xs = (const float4*)(xh + (size_t)sv[u] * 256);
            v0[u] = __ldg(xs + lane);
            v1[u] = __ldg(xs + lane + 32);
        }
#pragma unroll
        for (int u = 0; u < 4; u++) {
            s0 += a0[u]; s1 += a1[u];
            f0[0] = fmaf(a0[u], v0[u].x, f0[0]); f0[1] = fmaf(a0[u], v0[u].y, f0[1]);
            f0[2] = fmaf(a0[u], v0[u].z, f0[2]); f0[3] = fmaf(a0[u], v0[u].w, f0[3]);
            f1[0] = fmaf(a1[u], v1[u].x, f1[0]); f1[1] = fmaf(a1[u], v1[u].y, f1[1]);
            f1[2] = fmaf(a1[u], v1[u].z, f1[2]); f1[3] = fmaf(a1[u], v1[u].w, f1[3]);
        }
    }
    for (; j < end; ++j) {
        int s = __ldg(&csr[j]);
        float l0 = as_[s * 2 + 0] + ad0; l0 = l0 > 0.f ? l0 : 0.2f * l0;
        float l1 = as_[s * 2 + 1] + ad1; l1 = l1 > 0.f ? l1 : 0.2f * l1;
        float a0 = __expf(l0 - m0), a1 = __expf(l1 - m1);
        s0 += a0; s1 += a1;
        const float4* xs = (const float4*)(xh + (size_t)s * 256);
        float4 v0 = __ldg(xs + lane);
        float4 v1 = __ldg(xs + lane + 32);
        f0[0] = fmaf(a0, v0.x, f0[0]); f0[1] = fmaf(a0, v0.y, f0[1]);
        f0[2] = fmaf(a0, v0.z, f0[2]); f0[3] = fmaf(a0, v0.w, f0[3]);
        f1[0] = fmaf(a1, v1.x, f1[0]); f1[1] = fmaf(a1, v1.y, f1[1]);
        f1[2] = fmaf(a1, v1.z, f1[2]); f1[3] = fmaf(a1, v1.w, f1[3]);
    }
    float i0 = 1.0f / (s0 + 1e-16f), i1 = 1.0f / (s1 + 1e-16f);
    float4 o0, o1;
    const float4* b0 = (const float4*)bias;
    float4 bb0 = b0[lane], bb1 = b0[lane + 32];
    o0.x = f0[0] * i0 + bb0.x; o0.y = f0[1] * i0 + bb0.y;
    o0.z = f0[2] * i0 + bb0.z; o0.w = f0[3] * i0 + bb0.w;
    o1.x = f1[0] * i1 + bb1.x; o1.y = f1[1] * i1 + bb1.y;
    o1.z = f1[2] * i1 + bb1.z; o1.w = f1[3] * i1 + bb1.w;
    o0.x = o0.x > 0.f ? o0.x : expm1f(o0.x);
    o0.y = o0.y > 0.f ? o0.y : expm1f(o0.y);
    o0.z = o0.z > 0.f ? o0.z : expm1f(o0.z);
    o0.w = o0.w > 0.f ? o0.w : expm1f(o0.w);
    o1.x = o1.x > 0.f ? o1.x : expm1f(o1.x);
    o1.y = o1.y > 0.f ? o1.y : expm1f(o1.y);
    o1.z = o1.z > 0.f ? o1.z : expm1f(o1.z);
    o1.w = o1.w > 0.f ? o1.w : expm1f(o1.w);
    float4* op = (float4*)(out + (size_t)d * 256);
    op[lane] = o0;
    op[lane + 32] = o1;
}

// GAT head=1, ch=64; unrolled x4; writes (agg + bias) * scale
__global__ __launch_bounds__(256) void gat_pull_1_64(
        const int* __restrict__ rs, const int* __restrict__ csr,
        const float* __restrict__ as_, const float* __restrict__ ad_,
        const float* __restrict__ xh, const float* __restrict__ bias,
        const float* __restrict__ scale, float* __restrict__ out,
        int ostride, int ooff) {
    int d = (blockIdx.x * blockDim.x + threadIdx.x) >> 5;
    int lane = threadIdx.x & 31;
    if (d >= NN) return;
    int beg = rs[d], end = rs[d + 1];
    float add = ad_[d];
    float m = -INFINITY;
    for (int j = beg + lane; j < end; j += 32) {
        int s = __ldg(&csr[j]);
        float l = as_[s] + add; l = l > 0.f ? l : 0.2f * l;
        m = fmaxf(m, l);
    }
#pragma unroll
    for (int o = 16; o; o >>= 1) m = fmaxf(m, __shfl_xor_sync(0xFFFFFFFFu, m, o));
    float ssum = 0.f, f0 = 0.f, f1 = 0.f;
    int j = beg;
    for (; j + 4 <= end; j += 4) {
        int sv[4];
#pragma unroll
        for (int u = 0; u < 4; u++) sv[u] = __ldg(&csr[j + u]);
        float a[4];
#pragma unroll
        for (int u = 0; u < 4; u++) {
            float l = as_[sv[u]] + add; l = l > 0.f ? l : 0.2f * l;
            a[u] = __expf(l - m);
        }
        float2 v[4];
#pragma unroll
        for (int u = 0; u < 4; u++)
            v[u] = __ldg((const float2*)(xh + (size_t)sv[u] * 64) + lane);
#pragma unroll
        for (int u = 0; u < 4; u++) {
            ssum += a[u];
            f0 = fmaf(a[u], v[u].x, f0); f1 = fmaf(a[u], v[u].y, f1);
        }
    }
    for (; j < end; ++j) {
        int s = __ldg(&csr[j]);
        float l = as_[s] + add; l = l > 0.f ? l : 0.2f * l;
        float a = __expf(l - m);
        ssum += a;
        float2 v = __ldg((const float2*)(xh + (size_t)s * 64) + lane);
        f0 = fmaf(a, v.x, f0); f1 = fmaf(a, v.y, f1);
    }
    float sc = scale[0];
    float inv = 1.0f / (ssum + 1e-16f);
    float2 o;
    o.x = (f0 * inv + bias[lane * 2 + 0]) * sc;
    o.y = (f1 * inv + bias[lane * 2 + 1]) * sc;
    ((float2*)(out + (size_t)d * ostride + ooff))[lane] = o;
}

// ---------------------------------------------------------------------------
// GCN pull (ch=128): warp per dst, unrolled x4, fused bias/relu.
// ---------------------------------------------------------------------------
__global__ __launch_bounds__(256) void gcn_pull_128(
        const int* __restrict__ rs, const int* __restrict__ csr,
        const float* __restrict__ dinv, const float* __restrict__ xw,
        const float* __restrict__ bias, float* __restrict__ out, int relu) {
    int d = (blockIdx.x * blockDim.x + threadIdx.x) >> 5;
    int lane = threadIdx.x & 31;
    if (d >= NN) return;
    int beg = rs[d], end = rs[d + 1];
    float dd = dinv[d];
    float f[4] = {0.f, 0.f, 0.f, 0.f};
    int j = beg;
    for (; j + 4 <= end; j += 4) {
        int sv[4];
#pragma unroll
        for (int u = 0; u < 4; u++) sv[u] = __ldg(&csr[j + u]);
        float nrm[4];
#pragma unroll
        for (int u = 0; u < 4; u++) nrm[u] = __ldg(&dinv[sv[u]]) * dd;
        float4 v[4];
#pragma unroll
        for (int u = 0; u < 4; u++)
            v[u] = __ldg((const float4*)(xw + (size_t)sv[u] * 128) + lane);
#pragma unroll
        for (int u = 0; u < 4; u++) {
            f[0] = fmaf(nrm[u], v[u].x, f[0]); f[1] = fmaf(nrm[u], v[u].y, f[1]);
            f[2] = fmaf(nrm[u], v[u].z, f[2]); f[3] = fmaf(nrm[u], v[u].w, f[3]);
        }
    }
    for (; j < end; ++j) {
        int s = __ldg(&csr[j]);
        float nrm = __ldg(&dinv[s]) * dd;
        float4 v = __ldg((const float4*)(xw + (size_t)s * 128) + lane);
        f[0] = fmaf(nrm, v.x, f[0]); f[1] = fmaf(nrm, v.y, f[1]);
        f[2] = fmaf(nrm, v.z, f[2]); f[3] = fmaf(nrm, v.w, f[3]);
    }
    float4 bb = ((const float4*)bias)[lane];
    float4 o;
    o.x = f[0] + bb.x; o.y = f[1] + bb.y; o.z = f[2] + bb.z; o.w = f[3] + bb.w;
    if (relu) {
        o.x = fmaxf(o.x, 0.f); o.y = fmaxf(o.y, 0.f);
        o.z = fmaxf(o.z, 0.f); o.w = fmaxf(o.w, 0.f);
    }
    ((float4*)(out + (size_t)d * 128))[lane] = o;
}

// GCN ch=64; unrolled x4; writes (agg + bias) * scale
__global__ __launch_bounds__(256) void gcn_pull_64(
        const int* __restrict__ rs, const int* __restrict__ csr,
        const float* __restrict__ dinv, const float* __restrict__ xw,
        const float* __restrict__ bias, const float* __restrict__ scale,
        float* __restrict__ out, int ostride, int ooff) {
    int d = (blockIdx.x * blockDim.x + threadIdx.x) >> 5;
    int lane = threadIdx.x & 31;
    if (d >= NN) return;
    int beg = rs[d], end = rs[d + 1];
    float dd = dinv[d];
    float f0 = 0.f, f1 = 0.f;
    int j = beg;
    for (; j + 4 <= end; j += 4) {
        int sv[4];
#pragma unroll
        for (int u = 0; u < 4; u++) sv[u] = __ldg(&csr[j + u]);
        float nrm[4];
#pragma unroll
        for (int u = 0; u < 4; u++) nrm[u] = __ldg(&dinv[sv[u]]) * dd;
        float2 v[4];
#pragma unroll
        for (int u = 0; u < 4; u++)
            v[u] = __ldg((const float2*)(xw + (size_t)sv[u] * 64) + lane);
#pragma unroll
        for (int u = 0; u < 4; u++) {
            f0 = fmaf(nrm[u], v[u].x, f0); f1 = fmaf(nrm[u], v[u].y, f1);
        }
    }
    for (; j < end; ++j) {
        int s = __ldg(&csr[j]);
        float nrm = __ldg(&dinv[s]) * dd;
        float2 v = __ldg((const float2*)(xw + (size_t)s * 64) + lane);
        f0 = fmaf(nrm, v.x, f0); f1 = fmaf(nrm, v.y, f1);
    }
    float sc = scale[0];
    float2 o;
    o.x = (f0 + bias[lane * 2 + 0]) * sc;
    o.y = (f1 + bias[lane * 2 + 1]) * sc;
    ((float2*)(out + (size_t)d * ostride + ooff))[lane] = o;
}

// ---------------------------------------------------------------------------
static inline int cdiv(int a, int b) { return (a + b - 1) / b; }

extern "C" void kernel_launch(void* const* d_in, const int* in_sizes, int n_in,
                              void* d_out, int out_size) {
    const float* x      = (const float*)d_in[0];
    const int*   src    = (const int*)d_in[1];
    const int    E      = in_sizes[1] / 2;
    const int*   dst    = src + E;
    const float* gat1_W = (const float*)d_in[2];
    const float* att_s1 = (const float*)d_in[3];
    const float* att_d1 = (const float*)d_in[4];
    const float* gat1_b = (const float*)d_in[5];
    const float* gat2_W = (const float*)d_in[6];
    const float* att_s2 = (const float*)d_in[7];
    const float* att_d2 = (const float*)d_in[8];
    const float* gat2_b = (const float*)d_in[9];
    const float* gcn1_W = (const float*)d_in[10];
    const float* gcn1_b = (const float*)d_in[11];
    const float* gcn2_W = (const float*)d_in[12];
    const float* gcn2_b = (const float*)d_in[13];
    const float* lin1_W = (const float*)d_in[14];
    const float* lin1_b = (const float*)d_in[15];
    const float* lin2_W = (const float*)d_in[16];
    const float* lin2_b = (const float*)d_in[17];
    const float* lin3_W = (const float*)d_in[18];
    const float* lin3_b = (const float*)d_in[19];
    const float* wt     = (const float*)d_in[20];
    const float* wc     = (const float*)d_in[21];

    const int Etot = E + NN;

    float *xh1, *acc1, *as1, *ad1, *xh2, *as2, *ad2;
    float *xw1, *gcn1, *xw2, *dinv, *cat, *y1, *y2;
    int *counts, *rsp, *cursor, *csr;
    cudaGetSymbolAddress((void**)&xh1, g_xh1);
    cudaGetSymbolAddress((void**)&acc1, g_acc1);
    cudaGetSymbolAddress((void**)&as1, g_as1);
    cudaGetSymbolAddress((void**)&ad1, g_ad1);
    cudaGetSymbolAddress((void**)&xh2, g_xh2);
    cudaGetSymbolAddress((void**)&as2, g_as2);
    cudaGetSymbolAddress((void**)&ad2, g_ad2);
    cudaGetSymbolAddress((void**)&xw1, g_xw1);
    cudaGetSymbolAddress((void**)&gcn1, g_gcn1);
    cudaGetSymbolAddress((void**)&xw2, g_xw2);
    cudaGetSymbolAddress((void**)&dinv, g_dinv);
    cudaGetSymbolAddress((void**)&cat, g_cat);
    cudaGetSymbolAddress((void**)&y1, g_y1);
    cudaGetSymbolAddress((void**)&y2, g_y2);
    cudaGetSymbolAddress((void**)&counts, g_counts);
    cudaGetSymbolAddress((void**)&rsp, g_rs);
    cudaGetSymbolAddress((void**)&cursor, g_cursor);
    cudaGetSymbolAddress((void**)&csr, g_csr);

    const int TB = 256;
    const int GY = NN / 64;   // 625

    // ---- CSR build (dst-grouped src list) ----
    zero_int_kernel<<<cdiv(NN, TB), TB>>>(counts, NN);
    hist_kernel<<<cdiv(Etot, TB), TB>>>(dst, counts, E, Etot);
    scan_kernel<<<1, 1024>>>(counts, rsp, cursor, NN);
    csr_fill_kernel<<<cdiv(Etot, TB), TB>>>(src, dst, cursor, csr, E, Etot);
    dinv_kernel<<<cdiv(NN, TB), TB>>>(counts, dinv, NN);

    // ---- dense projections from x ----
    gemm_tf32_kernel<128><<<dim3(2, GY), 256>>>(x, gat1_W, nullptr, xh1, 256, 128);
    gemm_tf32_kernel<128><<<dim3(1, GY), 256>>>(x, gcn1_W, nullptr, xw1, 128, 128);

    // ---- GAT layer 1 (heads=2, ch=128) ----
    att_kernel<<<cdiv(NN * 2 * 32, TB), TB>>>(xh1, att_s1, att_d1, as1, ad1, NN * 2, 2, 128);
    gat_pull_2_128<<<cdiv(NN * 32, TB), TB>>>(rsp, csr, as1, ad1, xh1, gat1_b, acc1);

    // ---- GAT layer 2 (heads=1, ch=64) -> cat[:, 64:128] * wt ----
    gemm_tf32_kernel<64><<<dim3(1, GY), 256>>>(acc1, gat2_W, nullptr, xh2, 64, 256);
    att_kernel<<<cdiv(NN * 32, TB), TB>>>(xh2, att_s2, att_d2, as2, ad2, NN, 1, 64);
    gat_pull_1_64<<<cdiv(NN * 32, TB), TB>>>(rsp, csr, as2, ad2, xh2, gat2_b, wt, cat, 128, 64);

    // ---- GCN layer 1 (relu fused) ----
    gcn_pull_128<<<cdiv(NN * 32, TB), TB>>>(rsp, csr, dinv, xw1, gcn1_b, gcn1, 1);

    // ---- GCN layer 2 -> cat[:, 0:64] * wc ----
    gemm_tf32_kernel<64><<<dim3(1, GY), 256>>>(gcn1, gcn2_W, nullptr, xw2, 64, 128);
    gcn_pull_64<<<cdiv(NN * 32, TB), TB>>>(rsp, csr, dinv, xw2, gcn2_b, wc, cat, 128, 0);

    // ---- MLP head ----
    gemm_tf32_kernel<128><<<dim3(2, GY), 256>>>(cat, lin1_W, lin1_b, y1, 256, 128);
    gemm_tf32_kernel<128><<<dim3(1, GY), 256>>>(y1, lin2_W, lin2_b, y2, 128, 256);
    gemm_tf32_kernel<64><<<dim3(1, GY), 256>>>(y2, lin3_W, lin3_b, (float*)d_out, 64, 128);
}

// round 12
// speedup vs baseline: 1.0858x; 1.0858x over previous
#include <cuda_runtime.h>
#include <stdint.h>
#include <math.h>

#define NN 40000
#define MAXE 700000   // E (640k) + self loops (40k) with slack

// ---------------------------------------------------------------------------
// Scratch (device globals)
// ---------------------------------------------------------------------------
__device__ float g_xh1[NN * 256];   // x @ gat1_W
__device__ float g_acc1[NN * 256];  // GAT1 output
__device__ float g_as1[NN * 2];
__device__ float g_ad1[NN * 2];
__device__ float g_xh2[NN * 64];    // gat1out @ gat2_W
__device__ float g_as2[NN];
__device__ float g_ad2[NN];
__device__ float g_xw1[NN * 128];   // x @ gcn1_W
__device__ float g_gcn1[NN * 128];  // GCN1 output
__device__ float g_xw2[NN * 64];
__device__ float g_dinv[NN];
__device__ float g_cat[NN * 128];   // [gcn2*wc | gat2*wt]
__device__ float g_y1[NN * 256];
__device__ float g_y2[NN * 128];
// CSR scratch
__device__ int g_counts[NN];
__device__ int g_rs[NN + 1];
__device__ int g_cursor[NN];
__device__ int g_csr[MAXE];         // src ids grouped by dst

// ---------------------------------------------------------------------------
// CSR build
// ---------------------------------------------------------------------------
__global__ void zero_int_kernel(int* p, int n) {
    int i = blockIdx.x * blockDim.x + threadIdx.x;
    if (i < n) p[i] = 0;
}

__global__ void hist_kernel(const int* __restrict__ dst, int* __restrict__ counts,
                            int E, int Etot) {
    int t = blockIdx.x * blockDim.x + threadIdx.x;
    if (t >= Etot) return;
    int d = (t < E) ? dst[t] : (t - E);
    atomicAdd(&counts[d], 1);
}

// single-block exclusive scan of 40k counts -> rs (and cursor), rs[n] = total
__global__ void scan_kernel(const int* __restrict__ counts, int* __restrict__ rs,
                            int* __restrict__ cursor, int n) {
    __shared__ int sums[1024];
    int t = threadIdx.x;
    int per = (n + 1023) >> 10;
    int beg = t * per;
    int end = min(beg + per, n);
    int s = 0;
    for (int i = beg; i < end; i++) s += counts[i];
    sums[t] = s;
    __syncthreads();
    for (int off = 1; off < 1024; off <<= 1) {
        int v = (t >= off) ? sums[t - off] : 0;
        __syncthreads();
        sums[t] += v;
        __syncthreads();
    }
    int base = (t == 0) ? 0 : sums[t - 1];
    for (int i = beg; i < end; i++) {
        rs[i] = base;
        cursor[i] = base;
        base += counts[i];
    }
    if (beg < n && end == n) rs[n] = base;
}

__global__ void csr_fill_kernel(const int* __restrict__ src, const int* __restrict__ dst,
                                int* __restrict__ cursor, int* __restrict__ csr,
                                int E, int Etot) {
    int t = blockIdx.x * blockDim.x + threadIdx.x;
    if (t >= Etot) return;
    int s = (t < E) ? src[t] : (t - E);
    int d = (t < E) ? dst[t] : (t - E);
    int pos = atomicAdd(&cursor[d], 1);
    csr[pos] = s;
}

__global__ void dinv_kernel(const int* __restrict__ counts, float* __restrict__ dinv, int n) {
    int t = blockIdx.x * blockDim.x + threadIdx.x;
    if (t >= n) return;
    dinv[t] = rsqrtf(fmaxf((float)counts[t], 1.0f));
}

// ---------------------------------------------------------------------------
// TF32 tensor-core GEMM (identical to round 10/11)
// ---------------------------------------------------------------------------
__device__ __forceinline__ uint32_t f2tf(float x) {
    uint32_t r;
    asm("cvt.rna.tf32.f32 %0, %1;" : "=r"(r) : "f"(x));
    return r;
}

__device__ __forceinline__ void mma_tf32(float* c, const uint32_t* a, const uint32_t* b) {
    asm volatile(
        "mma.sync.aligned.m16n8k8.row.col.f32.tf32.tf32.f32 "
        "{%0,%1,%2,%3}, {%4,%5,%6,%7}, {%8,%9}, {%0,%1,%2,%3};"
        : "+f"(c[0]), "+f"(c[1]), "+f"(c[2]), "+f"(c[3])
        : "r"(a[0]), "r"(a[1]), "r"(a[2]), "r"(a[3]), "r"(b[0]), "r"(b[1]));
}

template <int BN>
__global__ __launch_bounds__(256) void gemm_tf32_kernel(
        const float* __restrict__ A, const float* __restrict__ B,
        const float* __restrict__ bias, float* __restrict__ C,
        int Nc, int K) {
    constexpr int WN = BN / 4;
    constexpr int NT = WN / 8;
    constexpr int NB4 = BN / 4;
    constexpr int BLD = (BN == 128) ? 4 : 2;
    __shared__ float As[64][36];
    __shared__ float Bs[32][BN + 8];

    const int t = threadIdx.x;
    const int lane = t & 31;
    const int w = t >> 5;
    const int wm = w & 1;
    const int wn = w >> 1;
    const int row0 = blockIdx.y * 64;
    const int col0 = blockIdx.x * BN;

    const int ar0 = t >> 3, acc4_0 = (t & 7) * 4;
    const int ar1 = (t + 256) >> 3, acc4_1 = acc4_0;

    float acc[2][NT][4];
#pragma unroll
    for (int mi = 0; mi < 2; mi++)
#pragma unroll
        for (int ni = 0; ni < NT; ni++)
#pragma unroll
            for (int q = 0; q < 4; q++) acc[mi][ni][q] = 0.0f;

    const int nch = K >> 5;

    float4 pa0, pa1, pb[BLD];
    pa0 = *(const float4*)&A[(size_t)(row0 + ar0) * K + acc4_0];
    pa1 = *(const float4*)&A[(size_t)(row0 + ar1) * K + acc4_1];
#pragma unroll
    for (int i = 0; i < BLD; i++) {
        int id = t + i * 256;
        int kr = id / NB4, c4 = (id % NB4) * 4;
        pb[i] = *(const float4*)&B[(size_t)kr * Nc + col0 + c4];
    }

    for (int ch = 0; ch < nch; ch++) {
        As[ar0][acc4_0 + 0] = __uint_as_float(f2tf(pa0.x));
        As[ar0][acc4_0 + 1] = __uint_as_float(f2tf(pa0.y));
        As[ar0][acc4_0 + 2] = __uint_as_float(f2tf(pa0.z));
        As[ar0][acc4_0 + 3] = __uint_as_float(f2tf(pa0.w));
        As[ar1][acc4_1 + 0] = __uint_as_float(f2tf(pa1.x));
        As[ar1][acc4_1 + 1] = __uint_as_float(f2tf(pa1.y));
        As[ar1][acc4_1 + 2] = __uint_as_float(f2tf(pa1.z));
        As[ar1][acc4_1 + 3] = __uint_as_float(f2tf(pa1.w));
#pragma unroll
        for (int i = 0; i < BLD; i++) {
            int id = t + i * 256;
            int kr = id / NB4, c4 = (id % NB4) * 4;
            Bs[kr][c4 + 0] = __uint_as_float(f2tf(pb[i].x));
            Bs[kr][c4 + 1] = __uint_as_float(f2tf(pb[i].y));
            Bs[kr][c4 + 2] = __uint_as_float(f2tf(pb[i].z));
            Bs[kr][c4 + 3] = __uint_as_float(f2tf(pb[i].w));
        }
        __syncthreads();

        if (ch + 1 < nch) {
            const int k0 = (ch + 1) << 5;
            pa0 = *(const float4*)&A[(size_t)(row0 + ar0) * K + k0 + acc4_0];
            pa1 = *(const float4*)&A[(size_t)(row0 + ar1) * K + k0 + acc4_1];
#pragma unroll
            for (int i = 0; i < BLD; i++) {
                int id = t + i * 256;
                int kr = id / NB4, c4 = (id % NB4) * 4;
                pb[i] = *(const float4*)&B[(size_t)(k0 + kr) * Nc + col0 + c4];
            }
        }

#pragma unroll
        for (int k8 = 0; k8 < 4; k8++) {
            const int kb = k8 * 8;
            uint32_t af[2][4];
#pragma unroll
            for (int mi = 0; mi < 2; mi++) {
                const int rb = wm * 32 + mi * 16 + (lane >> 2);
                const int cb = kb + (lane & 3);
                af[mi][0] = __float_as_uint(As[rb][cb]);
                af[mi][1] = __float_as_uint(As[rb + 8][cb]);
                af[mi][2] = __float_as_uint(As[rb][cb + 4]);
                af[mi][3] = __float_as_uint(As[rb + 8][cb + 4]);
            }
            uint32_t bf[NT][2];
#pragma unroll
            for (int ni = 0; ni < NT; ni++) {
                const int nb = wn * WN + ni * 8 + (lane >> 2);
                const int kk = kb + (lane & 3);
                bf[ni][0] = __float_as_uint(Bs[kk][nb]);
                bf[ni][1] = __float_as_uint(Bs[kk + 4][nb]);
            }
#pragma unroll
            for (int mi = 0; mi < 2; mi++)
#pragma unroll
                for (int ni = 0; ni < NT; ni++)
                    mma_tf32(acc[mi][ni], af[mi], bf[ni]);
        }
        __syncthreads();
    }

#pragma unroll
    for (int mi = 0; mi < 2; mi++) {
        const int rowa = row0 + wm * 32 + mi * 16 + (lane >> 2);
#pragma unroll
        for (int ni = 0; ni < NT; ni++) {
            const int col = col0 + wn * WN + ni * 8 + (lane & 3) * 2;
            float b0 = bias ? bias[col] : 0.0f;
            float b1 = bias ? bias[col + 1] : 0.0f;
            float2 s0, s1;
            s0.x = acc[mi][ni][0] + b0; s0.y = acc[mi][ni][1] + b1;
            s1.x = acc[mi][ni][2] + b0; s1.y = acc[mi][ni][3] + b1;
            *(float2*)&C[(size_t)rowa * Nc + col] = s0;
            *(float2*)&C[(size_t)(rowa + 8) * Nc + col] = s1;
        }
    }
}

// ---------------------------------------------------------------------------
// Attention logits: per 'row' of xh (row = node*heads + h)
// ---------------------------------------------------------------------------
__global__ void att_kernel(const float* __restrict__ xh, const float* __restrict__ a_src,
                           const float* __restrict__ a_dst, float* __restrict__ out_s,
                           float* __restrict__ out_d, int rows, int heads, int ch) {
    int w = (blockIdx.x * blockDim.x + threadIdx.x) >> 5;
    int lane = threadIdx.x & 31;
    if (w >= rows) return;
    const float* row = xh + (size_t)w * ch;
    const float* as = a_src + (size_t)(w % heads) * ch;
    const float* ad = a_dst + (size_t)(w % heads) * ch;
    float ss = 0.0f, dd = 0.0f;
    for (int c = lane; c < ch; c += 32) {
        float v = row[c];
        ss += v * as[c];
        dd += v * ad[c];
    }
#pragma unroll
    for (int o = 16; o; o >>= 1) {
        ss += __shfl_down_sync(0xFFFFFFFFu, ss, o);
        dd += __shfl_down_sync(0xFFFFFFFFu, dd, o);
    }
    if (lane == 0) { out_s[w] = ss; out_d[w] = dd; }
}

// ---------------------------------------------------------------------------
// GAT pull (heads=2, ch=128): warp per dst, edge loop unrolled x4.
// ---------------------------------------------------------------------------
__global__ __launch_bounds__(256) void gat_pull_2_128(
        const int* __restrict__ rs, const int* __restrict__ csr,
        const float* __restrict__ as_, const float* __restrict__ ad_,
        const float* __restrict__ xh, const float* __restrict__ bias,
        float* __restrict__ out) {
    int d = (blockIdx.x * blockDim.x + threadIdx.x) >> 5;
    int lane = threadIdx.x & 31;
    if (d >= NN) return;
    int beg = rs[d], end = rs[d + 1];
    float ad0 = ad_[d * 2 + 0], ad1 = ad_[d * 2 + 1];
    float m0 = -INFINITY, m1 = -INFINITY;
    for (int j = beg + lane; j < end; j += 32) {
        int s = __ldg(&csr[j]);
        float l0 = as_[s * 2 + 0] + ad0; l0 = l0 > 0.f ? l0 : 0.2f * l0;
        float l1 = as_[s * 2 + 1] + ad1; l1 = l1 > 0.f ? l1 : 0.2f * l1;
        m0 = fmaxf(m0, l0); m1 = fmaxf(m1, l1);
    }
#pragma unroll
    for (int o = 16; o; o >>= 1) {
        m0 = fmaxf(m0, __shfl_xor_sync(0xFFFFFFFFu, m0, o));
        m1 = fmaxf(m1, __shfl_xor_sync(0xFFFFFFFFu, m1, o));
    }
    float s0 = 0.f, s1 = 0.f;
    float f0[4] = {0.f, 0.f, 0.f, 0.f};
    float f1[4] = {0.f, 0.f, 0.f, 0.f};
    int j = beg;
    for (; j + 4 <= end; j += 4) {
        int sv[4];
#pragma unroll
        for (int u = 0; u < 4; u++) sv[u] = __ldg(&csr[j + u]);
        float a0[4], a1[4];
#pragma unroll
        for (int u = 0; u < 4; u++) {
            float l0 = as_[sv[u] * 2 + 0] + ad0; l0 = l0 > 0.f ? l0 : 0.2f * l0;
            float l1 = as_[sv[u] * 2 + 1] + ad1; l1 = l1 > 0.f ? l1 : 0.2f * l1;
            a0[u] = __expf(l0 - m0); a1[u] = __expf(l1 - m1);
        }
        float4 v0[4], v1[4];
#pragma unroll
        for (int u = 0; u < 4; u++) {
            const float4* xs = (const float4*)(xh + (size_t)sv[u] * 256);
            v0[u] = __ldg(xs + lane);
            v1[u] = __ldg(xs + lane + 32);
        }
#pragma unroll
        for (int u = 0; u < 4; u++) {
            s0 += a0[u]; s1 += a1[u];
            f0[0] = fmaf(a0[u], v0[u].x, f0[0]); f0[1] = fmaf(a0[u], v0[u].y, f0[1]);
            f0[2] = fmaf(a0[u], v0[u].z, f0[2]); f0[3] = fmaf(a0[u], v0[u].w, f0[3]);
            f1[0] = fmaf(a1[u], v1[u].x, f1[0]); f1[1] = fmaf(a1[u], v1[u].y, f1[1]);
            f1[2] = fmaf(a1[u], v1[u].z, f1[2]); f1[3] = fmaf(a1[u], v1[u].w, f1[3]);
        }
    }
    for (; j < end; ++j) {
        int s = __ldg(&csr[j]);
        float l0 = as_[s * 2 + 0] + ad0; l0 = l0 > 0.f ? l0 : 0.2f * l0;
        float l1 = as_[s * 2 + 1] + ad1; l1 = l1 > 0.f ? l1 : 0.2f * l1;
        float a0 = __expf(l0 - m0), a1 = __expf(l1 - m1);
        s0 += a0; s1 += a1;
        const float4* xs = (const float4*)(xh + (size_t)s * 256);
        float4 v0 = __ldg(xs + lane);
        float4 v1 = __ldg(xs + lane + 32);
        f0[0] = fmaf(a0, v0.x, f0[0]); f0[1] = fmaf(a0, v0.y, f0[1]);
        f0[2] = fmaf(a0, v0.z, f0[2]); f0[3] = fmaf(a0, v0.w, f0[3]);
        f1[0] = fmaf(a1, v1.x, f1[0]); f1[1] = fmaf(a1, v1.y, f1[1]);
        f1[2] = fmaf(a1, v1.z, f1[2]); f1[3] = fmaf(a1, v1.w, f1[3]);
    }
    float i0 = 1.0f / (s0 + 1e-16f), i1 = 1.0f / (s1 + 1e-16f);
    float4 o0, o1;
    const float4* b0 = (const float4*)bias;
    float4 bb0 = b0[lane], bb1 = b0[lane + 32];
    o0.x = f0[0] * i0 + bb0.x; o0.y = f0[1] * i0 + bb0.y;
    o0.z = f0[2] * i0 + bb0.z; o0.w = f0[3] * i0 + bb0.w;
    o1.x = f1[0] * i1 + bb1.x; o1.y = f1[1] * i1 + bb1.y;
    o1.z = f1[2] * i1 + bb1.z; o1.w = f1[3] * i1 + bb1.w;
    o0.x = o0.x > 0.f ? o0.x : expm1f(o0.x);
    o0.y = o0.y > 0.f ? o0.y : expm1f(o0.y);
    o0.z = o0.z > 0.f ? o0.z : expm1f(o0.z);
    o0.w = o0.w > 0.f ? o0.w : expm1f(o0.w);
    o1.x = o1.x > 0.f ? o1.x : expm1f(o1.x);
    o1.y = o1.y > 0.f ? o1.y : expm1f(o1.y);
    o1.z = o1.z > 0.f ? o1.z : expm1f(o1.z);
    o1.w = o1.w > 0.f ? o1.w : expm1f(o1.w);
    float4* op = (float4*)(out + (size_t)d * 256);
    op[lane] = o0;
    op[lane + 32] = o1;
}

// GAT head=1, ch=64; unrolled x4; writes (agg + bias) * scale
__global__ __launch_bounds__(256) void gat_pull_1_64(
        const int* __restrict__ rs, const int* __restrict__ csr,
        const float* __restrict__ as_, const float* __restrict__ ad_,
        const float* __restrict__ xh, const float* __restrict__ bias,
        const float* __restrict__ scale, float* __restrict__ out,
        int ostride, int ooff) {
    int d = (blockIdx.x * blockDim.x + threadIdx.x) >> 5;
    int lane = threadIdx.x & 31;
    if (d >= NN) return;
    int beg = rs[d], end = rs[d + 1];
    float add = ad_[d];
    float m = -INFINITY;
    for (int j = beg + lane; j < end; j += 32) {
        int s = __ldg(&csr[j]);
        float l = as_[s] + add; l = l > 0.f ? l : 0.2f * l;
        m = fmaxf(m, l);
    }
#pragma unroll
    for (int o = 16; o; o >>= 1) m = fmaxf(m, __shfl_xor_sync(0xFFFFFFFFu, m, o));
    float ssum = 0.f, f0 = 0.f, f1 = 0.f;
    int j = beg;
    for (; j + 4 <= end; j += 4) {
        int sv[4];
#pragma unroll
        for (int u = 0; u < 4; u++) sv[u] = __ldg(&csr[j + u]);
        float a[4];
#pragma unroll
        for (int u = 0; u < 4; u++) {
            float l = as_[sv[u]] + add; l = l > 0.f ? l : 0.2f * l;
            a[u] = __expf(l - m);
        }
        float2 v[4];
#pragma unroll
        for (int u = 0; u < 4; u++)
            v[u] = __ldg((const float2*)(xh + (size_t)sv[u] * 64) + lane);
#pragma unroll
        for (int u = 0; u < 4; u++) {
            ssum += a[u];
            f0 = fmaf(a[u], v[u].x, f0); f1 = fmaf(a[u], v[u].y, f1);
        }
    }
    for (; j < end; ++j) {
        int s = __ldg(&csr[j]);
        float l = as_[s] + add; l = l > 0.f ? l : 0.2f * l;
        float a = __expf(l - m);
        ssum += a;
        float2 v = __ldg((const float2*)(xh + (size_t)s * 64) + lane);
        f0 = fmaf(a, v.x, f0); f1 = fmaf(a, v.y, f1);
    }
    float sc = scale[0];
    float inv = 1.0f / (ssum + 1e-16f);
    float2 o;
    o.x = (f0 * inv + bias[lane * 2 + 0]) * sc;
    o.y = (f1 * inv + bias[lane * 2 + 1]) * sc;
    ((float2*)(out + (size_t)d * ostride + ooff))[lane] = o;
}

// ---------------------------------------------------------------------------
// GCN pull (ch=128): warp per dst, unrolled x4, fused bias/relu.
// ---------------------------------------------------------------------------
__global__ __launch_bounds__(256) void gcn_pull_128(
        const int* __restrict__ rs, const int* __restrict__ csr,
        const float* __restrict__ dinv, const float* __restrict__ xw,
        const float* __restrict__ bias, float* __restrict__ out, int relu) {
    int d = (blockIdx.x * blockDim.x + threadIdx.x) >> 5;
    int lane = threadIdx.x & 31;
    if (d >= NN) return;
    int beg = rs[d], end = rs[d + 1];
    float dd = dinv[d];
    float f[4] = {0.f, 0.f, 0.f, 0.f};
    int j = beg;
    for (; j + 4 <= end; j += 4) {
        int sv[4];
#pragma unroll
        for (int u = 0; u < 4; u++) sv[u] = __ldg(&csr[j + u]);
        float nrm[4];
#pragma unroll
        for (int u = 0; u < 4; u++) nrm[u] = __ldg(&dinv[sv[u]]) * dd;
        float4 v[4];
#pragma unroll
        for (int u = 0; u < 4; u++)
            v[u] = __ldg((const float4*)(xw + (size_t)sv[u] * 128) + lane);
#pragma unroll
        for (int u = 0; u < 4; u++) {
            f[0] = fmaf(nrm[u], v[u].x, f[0]); f[1] = fmaf(nrm[u], v[u].y, f[1]);
            f[2] = fmaf(nrm[u], v[u].z, f[2]); f[3] = fmaf(nrm[u], v[u].w, f[3]);
        }
    }
    for (; j < end; ++j) {
        int s = __ldg(&csr[j]);
        float nrm = __ldg(&dinv[s]) * dd;
        float4 v = __ldg((const float4*)(xw + (size_t)s * 128) + lane);
        f[0] = fmaf(nrm, v.x, f[0]); f[1] = fmaf(nrm, v.y, f[1]);
        f[2] = fmaf(nrm, v.z, f[2]); f[3] = fmaf(nrm, v.w, f[3]);
    }
    float4 bb = ((const float4*)bias)[lane];
    float4 o;
    o.x = f[0] + bb.x; o.y = f[1] + bb.y; o.z = f[2] + bb.z; o.w = f[3] + bb.w;
    if (relu) {
        o.x = fmaxf(o.x, 0.f); o.y = fmaxf(o.y, 0.f);
        o.z = fmaxf(o.z, 0.f); o.w = fmaxf(o.w, 0.f);
    }
    ((float4*)(out + (size_t)d * 128))[lane] = o;
}

// GCN ch=64; unrolled x4; writes (agg + bias) * scale
__global__ __launch_bounds__(256) void gcn_pull_64(
        const int* __restrict__ rs, const int* __restrict__ csr,
        const float* __restrict__ dinv, const float* __restrict__ xw,
        const float* __restrict__ bias, const float* __restrict__ scale,
        float* __restrict__ out, int ostride, int ooff) {
    int d = (blockIdx.x * blockDim.x + threadIdx.x) >> 5;
    int lane = threadIdx.x & 31;
    if (d >= NN) return;
    int beg = rs[d], end = rs[d + 1];
    float dd = dinv[d];
    float f0 = 0.f, f1 = 0.f;
    int j = beg;
    for (; j + 4 <= end; j += 4) {
        int sv[4];
#pragma unroll
        for (int u = 0; u < 4; u++) sv[u] = __ldg(&csr[j + u]);
        float nrm[4];
#pragma unroll
        for (int u = 0; u < 4; u++) nrm[u] = __ldg(&dinv[sv[u]]) * dd;
        float2 v[4];
#pragma unroll
        for (int u = 0; u < 4; u++)
            v[u] = __ldg((const float2*)(xw + (size_t)sv[u] * 64) + lane);
#pragma unroll
        for (int u = 0; u < 4; u++) {
            f0 = fmaf(nrm[u], v[u].x, f0); f1 = fmaf(nrm[u], v[u].y, f1);
        }
    }
    for (; j < end; ++j) {
        int s = __ldg(&csr[j]);
        float nrm = __ldg(&dinv[s]) * dd;
        float2 v = __ldg((const float2*)(xw + (size_t)s * 64) + lane);
        f0 = fmaf(nrm, v.x, f0); f1 = fmaf(nrm, v.y, f1);
    }
    float sc = scale[0];
    float2 o;
    o.x = (f0 + bias[lane * 2 + 0]) * sc;
    o.y = (f1 + bias[lane * 2 + 1]) * sc;
    ((float2*)(out + (size_t)d * ostride + ooff))[lane] = o;
}

// ---------------------------------------------------------------------------
static inline int cdiv(int a, int b) { return (a + b - 1) / b; }

extern "C" void kernel_launch(void* const* d_in, const int* in_sizes, int n_in,
                              void* d_out, int out_size) {
    const float* x      = (const float*)d_in[0];
    const int*   src    = (const int*)d_in[1];
    const int    E      = in_sizes[1] / 2;
    const int*   dst    = src + E;
    const float* gat1_W = (const float*)d_in[2];
    const float* att_s1 = (const float*)d_in[3];
    const float* att_d1 = (const float*)d_in[4];
    const float* gat1_b = (const float*)d_in[5];
    const float* gat2_W = (const float*)d_in[6];
    const float* att_s2 = (const float*)d_in[7];
    const float* att_d2 = (const float*)d_in[8];
    const float* gat2_b = (const float*)d_in[9];
    const float* gcn1_W = (const float*)d_in[10];
    const float* gcn1_b = (const float*)d_in[11];
    const float* gcn2_W = (const float*)d_in[12];
    const float* gcn2_b = (const float*)d_in[13];
    const float* lin1_W = (const float*)d_in[14];
    const float* lin1_b = (const float*)d_in[15];
    const float* lin2_W = (const float*)d_in[16];
    const float* lin2_b = (const float*)d_in[17];
    const float* lin3_W = (const float*)d_in[18];
    const float* lin3_b = (const float*)d_in[19];
    const float* wt     = (const float*)d_in[20];
    const float* wc     = (const float*)d_in[21];

    const int Etot = E + NN;

    float *xh1, *acc1, *as1, *ad1, *xh2, *as2, *ad2;
    float *xw1, *gcn1, *xw2, *dinv, *cat, *y1, *y2;
    int *counts, *rsp, *cursor, *csr;
    cudaGetSymbolAddress((void**)&xh1, g_xh1);
    cudaGetSymbolAddress((void**)&acc1, g_acc1);
    cudaGetSymbolAddress((void**)&as1, g_as1);
    cudaGetSymbolAddress((void**)&ad1, g_ad1);
    cudaGetSymbolAddress((void**)&xh2, g_xh2);
    cudaGetSymbolAddress((void**)&as2, g_as2);
    cudaGetSymbolAddress((void**)&ad2, g_ad2);
    cudaGetSymbolAddress((void**)&xw1, g_xw1);
    cudaGetSymbolAddress((void**)&gcn1, g_gcn1);
    cudaGetSymbolAddress((void**)&xw2, g_xw2);
    cudaGetSymbolAddress((void**)&dinv, g_dinv);
    cudaGetSymbolAddress((void**)&cat, g_cat);
    cudaGetSymbolAddress((void**)&y1, g_y1);
    cudaGetSymbolAddress((void**)&y2, g_y2);
    cudaGetSymbolAddress((void**)&counts, g_counts);
    cudaGetSymbolAddress((void**)&rsp, g_rs);
    cudaGetSymbolAddress((void**)&cursor, g_cursor);
    cudaGetSymbolAddress((void**)&csr, g_csr);

    // Side streams/events for fork-join graph parallelism (created once;
    // host-side driver objects only — no device memory involved).
    static cudaStream_t s2 = nullptr, s3 = nullptr;
    static cudaEvent_t e0 = nullptr, eCSR = nullptr, eXH1 = nullptr, eGCN = nullptr;
    if (!s2) {
        cudaStreamCreateWithFlags(&s2, cudaStreamNonBlocking);
        cudaStreamCreateWithFlags(&s3, cudaStreamNonBlocking);
        cudaEventCreateWithFlags(&e0, cudaEventDisableTiming);
        cudaEventCreateWithFlags(&eCSR, cudaEventDisableTiming);
        cudaEventCreateWithFlags(&eXH1, cudaEventDisableTiming);
        cudaEventCreateWithFlags(&eGCN, cudaEventDisableTiming);
    }

    const int TB = 256;
    const int GY = NN / 64;   // 625

    // ---- fork ----
    cudaEventRecord(e0, 0);
    cudaStreamWaitEvent(s2, e0, 0);
    cudaStreamWaitEvent(s3, e0, 0);

    // ---- origin stream: CSR build ----
    zero_int_kernel<<<cdiv(NN, TB), TB>>>(counts, NN);
    hist_kernel<<<cdiv(Etot, TB), TB>>>(dst, counts, E, Etot);
    scan_kernel<<<1, 1024>>>(counts, rsp, cursor, NN);
    csr_fill_kernel<<<cdiv(Etot, TB), TB>>>(src, dst, cursor, csr, E, Etot);
    dinv_kernel<<<cdiv(NN, TB), TB>>>(counts, dinv, NN);
    cudaEventRecord(eCSR, 0);

    // ---- s2: GAT projection + logits ----
    gemm_tf32_kernel<128><<<dim3(2, GY), 256, 0, s2>>>(x, gat1_W, nullptr, xh1, 256, 128);
    att_kernel<<<cdiv(NN * 2 * 32, TB), TB, 0, s2>>>(xh1, att_s1, att_d1, as1, ad1, NN * 2, 2, 128);
    cudaEventRecord(eXH1, s2);

    // ---- s3: GCN chain ----
    gemm_tf32_kernel<128><<<dim3(1, GY), 256, 0, s3>>>(x, gcn1_W, nullptr, xw1, 128, 128);
    cudaStreamWaitEvent(s3, eCSR, 0);
    gcn_pull_128<<<cdiv(NN * 32, TB), TB, 0, s3>>>(rsp, csr, dinv, xw1, gcn1_b, gcn1, 1);
    gemm_tf32_kernel<64><<<dim3(1, GY), 256, 0, s3>>>(gcn1, gcn2_W, nullptr, xw2, 64, 128);
    gcn_pull_64<<<cdiv(NN * 32, TB), TB, 0, s3>>>(rsp, csr, dinv, xw2, gcn2_b, wc, cat, 128, 0);
    cudaEventRecord(eGCN, s3);

    // ---- origin stream: GAT chain (CSR already ordered here) ----
    cudaStreamWaitEvent(0, eXH1, 0);
    gat_pull_2_128<<<cdiv(NN * 32, TB), TB>>>(rsp, csr, as1, ad1, xh1, gat1_b, acc1);
    gemm_tf32_kernel<64><<<dim3(1, GY), 256>>>(acc1, gat2_W, nullptr, xh2, 64, 256);
    att_kernel<<<cdiv(NN * 32, TB), TB>>>(xh2, att_s2, att_d2, as2, ad2, NN, 1, 64);
    gat_pull_1_64<<<cdiv(NN * 32, TB), TB>>>(rsp, csr, as2, ad2, xh2, gat2_b, wt, cat, 128, 64);

    // ---- join + MLP head ----
    cudaStreamWaitEvent(0, eGCN, 0);
    gemm_tf32_kernel<128><<<dim3(2, GY), 256>>>(cat, lin1_W, lin1_b, y1, 256, 128);
    gemm_tf32_kernel<128><<<dim3(1, GY), 256>>>(y1, lin2_W, lin2_b, y2, 128, 256);
    gemm_tf32_kernel<64><<<dim3(1, GY), 256>>>(y2, lin3_W, lin3_b, (float*)d_out, 64, 128);
}

// round 13
// speedup vs baseline: 1.0860x; 1.0002x over previous
#include <cuda_runtime.h>
#include <stdint.h>
#include <math.h>

#define NN 40000
#define MAXE 700000   // E (640k) + self loops (40k) with slack

// ---------------------------------------------------------------------------
// Scratch (device globals)
// ---------------------------------------------------------------------------
__device__ float g_agg1[NN * 256];  // GAT1 per-head alpha-weighted sums of x
__device__ float g_acc1[NN * 256];  // GAT1 output (post proj+bias+ELU)
__device__ float g_as1[NN * 2];
__device__ float g_ad1[NN * 2];
__device__ float g_wa1s[2 * 128];   // W_h @ att_src_h
__device__ float g_wa1d[2 * 128];   // W_h @ att_dst_h
__device__ float g_xh2[NN * 64];    // gat1out @ gat2_W
__device__ float g_as2[NN];
__device__ float g_ad2[NN];
__device__ float g_xw1[NN * 128];   // x @ gcn1_W
__device__ float g_gcn1[NN * 128];  // GCN1 output
__device__ float g_xw2[NN * 64];
__device__ float g_dinv[NN];
__device__ float g_cat[NN * 128];   // [gcn2*wc | gat2*wt]
__device__ float g_y1[NN * 256];
__device__ float g_y2[NN * 128];
// CSR scratch
__device__ int g_counts[NN];
__device__ int g_rs[NN + 1];
__device__ int g_cursor[NN];
__device__ int g_csr[MAXE];         // src ids grouped by dst

// ---------------------------------------------------------------------------
// CSR build
// ---------------------------------------------------------------------------
__global__ void zero_int_kernel(int* p, int n) {
    int i = blockIdx.x * blockDim.x + threadIdx.x;
    if (i < n) p[i] = 0;
}

__global__ void hist_kernel(const int* __restrict__ dst, int* __restrict__ counts,
                            int E, int Etot) {
    int t = blockIdx.x * blockDim.x + threadIdx.x;
    if (t >= Etot) return;
    int d = (t < E) ? dst[t] : (t - E);
    atomicAdd(&counts[d], 1);
}

__global__ void scan_kernel(const int* __restrict__ counts, int* __restrict__ rs,
                            int* __restrict__ cursor, int n) {
    __shared__ int sums[1024];
    int t = threadIdx.x;
    int per = (n + 1023) >> 10;
    int beg = t * per;
    int end = min(beg + per, n);
    int s = 0;
    for (int i = beg; i < end; i++) s += counts[i];
    sums[t] = s;
    __syncthreads();
    for (int off = 1; off < 1024; off <<= 1) {
        int v = (t >= off) ? sums[t - off] : 0;
        __syncthreads();
        sums[t] += v;
        __syncthreads();
    }
    int base = (t == 0) ? 0 : sums[t - 1];
    for (int i = beg; i < end; i++) {
        rs[i] = base;
        cursor[i] = base;
        base += counts[i];
    }
    if (beg < n && end == n) rs[n] = base;
}

__global__ void csr_fill_kernel(const int* __restrict__ src, const int* __restrict__ dst,
                                int* __restrict__ cursor, int* __restrict__ csr,
                                int E, int Etot) {
    int t = blockIdx.x * blockDim.x + threadIdx.x;
    if (t >= Etot) return;
    int s = (t < E) ? src[t] : (t - E);
    int d = (t < E) ? dst[t] : (t - E);
    int pos = atomicAdd(&cursor[d], 1);
    csr[pos] = s;
}

__global__ void dinv_kernel(const int* __restrict__ counts, float* __restrict__ dinv, int n) {
    int t = blockIdx.x * blockDim.x + threadIdx.x;
    if (t >= n) return;
    dinv[t] = rsqrtf(fmaxf((float)counts[t], 1.0f));
}

// ---------------------------------------------------------------------------
// TF32 tensor-core GEMM with lda/ldb/ldc and optional fused ELU.
// Block tile 64 x BN, BK=32, 256 threads. M%64==0, cols%BN==0, K%32==0.
// act: 0 = none, 2 = ELU.
// ---------------------------------------------------------------------------
__device__ __forceinline__ uint32_t f2tf(float x) {
    uint32_t r;
    asm("cvt.rna.tf32.f32 %0, %1;" : "=r"(r) : "f"(x));
    return r;
}

__device__ __forceinline__ void mma_tf32(float* c, const uint32_t* a, const uint32_t* b) {
    asm volatile(
        "mma.sync.aligned.m16n8k8.row.col.f32.tf32.tf32.f32 "
        "{%0,%1,%2,%3}, {%4,%5,%6,%7}, {%8,%9}, {%0,%1,%2,%3};"
        : "+f"(c[0]), "+f"(c[1]), "+f"(c[2]), "+f"(c[3])
        : "r"(a[0]), "r"(a[1]), "r"(a[2]), "r"(a[3]), "r"(b[0]), "r"(b[1]));
}

template <int BN>
__global__ __launch_bounds__(256) void gemm_tf32_kernel(
        const float* __restrict__ A, const float* __restrict__ B,
        const float* __restrict__ bias, float* __restrict__ C,
        int K, int lda, int ldb, int ldc, int act) {
    constexpr int WN = BN / 4;
    constexpr int NT = WN / 8;
    constexpr int NB4 = BN / 4;
    constexpr int BLD = (BN == 128) ? 4 : 2;
    __shared__ float As[64][36];
    __shared__ float Bs[32][BN + 8];

    const int t = threadIdx.x;
    const int lane = t & 31;
    const int w = t >> 5;
    const int wm = w & 1;
    const int wn = w >> 1;
    const int row0 = blockIdx.y * 64;
    const int col0 = blockIdx.x * BN;

    const int ar0 = t >> 3, acc4_0 = (t & 7) * 4;
    const int ar1 = (t + 256) >> 3, acc4_1 = acc4_0;

    float acc[2][NT][4];
#pragma unroll
    for (int mi = 0; mi < 2; mi++)
#pragma unroll
        for (int ni = 0; ni < NT; ni++)
#pragma unroll
            for (int q = 0; q < 4; q++) acc[mi][ni][q] = 0.0f;

    const int nch = K >> 5;

    float4 pa0, pa1, pb[BLD];
    pa0 = *(const float4*)&A[(size_t)(row0 + ar0) * lda + acc4_0];
    pa1 = *(const float4*)&A[(size_t)(row0 + ar1) * lda + acc4_1];
#pragma unroll
    for (int i = 0; i < BLD; i++) {
        int id = t + i * 256;
        int kr = id / NB4, c4 = (id % NB4) * 4;
        pb[i] = *(const float4*)&B[(size_t)kr * ldb + col0 + c4];
    }

    for (int ch = 0; ch < nch; ch++) {
        As[ar0][acc4_0 + 0] = __uint_as_float(f2tf(pa0.x));
        As[ar0][acc4_0 + 1] = __uint_as_float(f2tf(pa0.y));
        As[ar0][acc4_0 + 2] = __uint_as_float(f2tf(pa0.z));
        As[ar0][acc4_0 + 3] = __uint_as_float(f2tf(pa0.w));
        As[ar1][acc4_1 + 0] = __uint_as_float(f2tf(pa1.x));
        As[ar1][acc4_1 + 1] = __uint_as_float(f2tf(pa1.y));
        As[ar1][acc4_1 + 2] = __uint_as_float(f2tf(pa1.z));
        As[ar1][acc4_1 + 3] = __uint_as_float(f2tf(pa1.w));
#pragma unroll
        for (int i = 0; i < BLD; i++) {
            int id = t + i * 256;
            int kr = id / NB4, c4 = (id % NB4) * 4;
            Bs[kr][c4 + 0] = __uint_as_float(f2tf(pb[i].x));
            Bs[kr][c4 + 1] = __uint_as_float(f2tf(pb[i].y));
            Bs[kr][c4 + 2] = __uint_as_float(f2tf(pb[i].z));
            Bs[kr][c4 + 3] = __uint_as_float(f2tf(pb[i].w));
        }
        __syncthreads();

        if (ch + 1 < nch) {
            const int k0 = (ch + 1) << 5;
            pa0 = *(const float4*)&A[(size_t)(row0 + ar0) * lda + k0 + acc4_0];
            pa1 = *(const float4*)&A[(size_t)(row0 + ar1) * lda + k0 + acc4_1];
#pragma unroll
            for (int i = 0; i < BLD; i++) {
                int id = t + i * 256;
                int kr = id / NB4, c4 = (id % NB4) * 4;
                pb[i] = *(const float4*)&B[(size_t)(k0 + kr) * ldb + col0 + c4];
            }
        }

#pragma unroll
        for (int k8 = 0; k8 < 4; k8++) {
            const int kb = k8 * 8;
            uint32_t af[2][4];
#pragma unroll
            for (int mi = 0; mi < 2; mi++) {
                const int rb = wm * 32 + mi * 16 + (lane >> 2);
                const int cb = kb + (lane & 3);
                af[mi][0] = __float_as_uint(As[rb][cb]);
                af[mi][1] = __float_as_uint(As[rb + 8][cb]);
                af[mi][2] = __float_as_uint(As[rb][cb + 4]);
                af[mi][3] = __float_as_uint(As[rb + 8][cb + 4]);
            }
            uint32_t bf[NT][2];
#pragma unroll
            for (int ni = 0; ni < NT; ni++) {
                const int nb = wn * WN + ni * 8 + (lane >> 2);
                const int kk = kb + (lane & 3);
                bf[ni][0] = __float_as_uint(Bs[kk][nb]);
                bf[ni][1] = __float_as_uint(Bs[kk + 4][nb]);
            }
#pragma unroll
            for (int mi = 0; mi < 2; mi++)
#pragma unroll
                for (int ni = 0; ni < NT; ni++)
                    mma_tf32(acc[mi][ni], af[mi], bf[ni]);
        }
        __syncthreads();
    }

#pragma unroll
    for (int mi = 0; mi < 2; mi++) {
        const int rowa = row0 + wm * 32 + mi * 16 + (lane >> 2);
#pragma unroll
        for (int ni = 0; ni < NT; ni++) {
            const int col = col0 + wn * WN + ni * 8 + (lane & 3) * 2;
            float b0 = bias ? bias[col] : 0.0f;
            float b1 = bias ? bias[col + 1] : 0.0f;
            float2 s0, s1;
            s0.x = acc[mi][ni][0] + b0; s0.y = acc[mi][ni][1] + b1;
            s1.x = acc[mi][ni][2] + b0; s1.y = acc[mi][ni][3] + b1;
            if (act == 2) {
                s0.x = s0.x > 0.f ? s0.x : expm1f(s0.x);
                s0.y = s0.y > 0.f ? s0.y : expm1f(s0.y);
                s1.x = s1.x > 0.f ? s1.x : expm1f(s1.x);
                s1.y = s1.y > 0.f ? s1.y : expm1f(s1.y);
            }
            *(float2*)&C[(size_t)rowa * ldc + col] = s0;
            *(float2*)&C[(size_t)(rowa + 8) * ldc + col] = s1;
        }
    }
}

// ---------------------------------------------------------------------------
// wa = W_h @ att_h for GAT1: one warp per k (0..127), 4 dots of length 128.
// was[h*128+k] = sum_c W[k, h*128+c] * att_s[h, c]   (same for wad)
// ---------------------------------------------------------------------------
__global__ void wa_kernel(const float* __restrict__ W, const float* __restrict__ atts,
                          const float* __restrict__ attd, float* __restrict__ was,
                          float* __restrict__ wad) {
    int k = (blockIdx.x * blockDim.x + threadIdx.x) >> 5;
    int lane = threadIdx.x & 31;
    if (k >= 128) return;
    float s0 = 0.f, s1 = 0.f, d0 = 0.f, d1 = 0.f;
    for (int c = lane; c < 128; c += 32) {
        float w0 = W[k * 256 + c], w1 = W[k * 256 + 128 + c];
        s0 += w0 * atts[c];       s1 += w1 * atts[128 + c];
        d0 += w0 * attd[c];       d1 += w1 * attd[128 + c];
    }
#pragma unroll
    for (int o = 16; o; o >>= 1) {
        s0 += __shfl_down_sync(0xFFFFFFFFu, s0, o);
        s1 += __shfl_down_sync(0xFFFFFFFFu, s1, o);
        d0 += __shfl_down_sync(0xFFFFFFFFu, d0, o);
        d1 += __shfl_down_sync(0xFFFFFFFFu, d1, o);
    }
    if (lane == 0) {
        was[k] = s0; was[128 + k] = s1;
        wad[k] = d0; wad[128 + k] = d1;
    }
}

// GAT1 logits straight from x: warp per node, 4 dots of length 128.
__global__ __launch_bounds__(256) void attx_kernel(
        const float* __restrict__ x, const float* __restrict__ was,
        const float* __restrict__ wad, float* __restrict__ as_, float* __restrict__ ad_) {
    int n = (blockIdx.x * blockDim.x + threadIdx.x) >> 5;
    int lane = threadIdx.x & 31;
    if (n >= NN) return;
    float4 xv = ((const float4*)(x + (size_t)n * 128))[lane];
    float4 ws0 = ((const float4*)was)[lane];
    float4 ws1 = ((const float4*)(was + 128))[lane];
    float4 wd0 = ((const float4*)wad)[lane];
    float4 wd1 = ((const float4*)(wad + 128))[lane];
    float s0 = xv.x * ws0.x + xv.y * ws0.y + xv.z * ws0.z + xv.w * ws0.w;
    float s1 = xv.x * ws1.x + xv.y * ws1.y + xv.z * ws1.z + xv.w * ws1.w;
    float d0 = xv.x * wd0.x + xv.y * wd0.y + xv.z * wd0.z + xv.w * wd0.w;
    float d1 = xv.x * wd1.x + xv.y * wd1.y + xv.z * wd1.z + xv.w * wd1.w;
#pragma unroll
    for (int o = 16; o; o >>= 1) {
        s0 += __shfl_down_sync(0xFFFFFFFFu, s0, o);
        s1 += __shfl_down_sync(0xFFFFFFFFu, s1, o);
        d0 += __shfl_down_sync(0xFFFFFFFFu, d0, o);
        d1 += __shfl_down_sync(0xFFFFFFFFu, d1, o);
    }
    if (lane == 0) {
        as_[n * 2 + 0] = s0; as_[n * 2 + 1] = s1;
        ad_[n * 2 + 0] = d0; ad_[n * 2 + 1] = d1;
    }
}

// ---------------------------------------------------------------------------
// GAT1 pull over raw x (128 ch): per-head alpha-weighted sums, normalized.
// agg[d, 0:128] = (sum a0 x_src)/s0 ; agg[d, 128:256] = (sum a1 x_src)/s1
// ---------------------------------------------------------------------------
__global__ __launch_bounds__(256) void gat_pull_agg(
        const int* __restrict__ rs, const int* __restrict__ csr,
        const float* __restrict__ as_, const float* __restrict__ ad_,
        const float* __restrict__ x, float* __restrict__ agg) {
    int d = (blockIdx.x * blockDim.x + threadIdx.x) >> 5;
    int lane = threadIdx.x & 31;
    if (d >= NN) return;
    int beg = rs[d], end = rs[d + 1];
    float ad0 = ad_[d * 2 + 0], ad1 = ad_[d * 2 + 1];
    float m0 = -INFINITY, m1 = -INFINITY;
    for (int j = beg + lane; j < end; j += 32) {
        int s = __ldg(&csr[j]);
        float l0 = as_[s * 2 + 0] + ad0; l0 = l0 > 0.f ? l0 : 0.2f * l0;
        float l1 = as_[s * 2 + 1] + ad1; l1 = l1 > 0.f ? l1 : 0.2f * l1;
        m0 = fmaxf(m0, l0); m1 = fmaxf(m1, l1);
    }
#pragma unroll
    for (int o = 16; o; o >>= 1) {
        m0 = fmaxf(m0, __shfl_xor_sync(0xFFFFFFFFu, m0, o));
        m1 = fmaxf(m1, __shfl_xor_sync(0xFFFFFFFFu, m1, o));
    }
    float s0 = 0.f, s1 = 0.f;
    float f0[4] = {0.f, 0.f, 0.f, 0.f};
    float f1[4] = {0.f, 0.f, 0.f, 0.f};
    for (int j = beg; j < end; ++j) {
        int s = __ldg(&csr[j]);
        float l0 = as_[s * 2 + 0] + ad0; l0 = l0 > 0.f ? l0 : 0.2f * l0;
        float l1 = as_[s * 2 + 1] + ad1; l1 = l1 > 0.f ? l1 : 0.2f * l1;
        float a0 = __expf(l0 - m0), a1 = __expf(l1 - m1);
        s0 += a0; s1 += a1;
        float4 v = __ldg((const float4*)(x + (size_t)s * 128) + lane);
        f0[0] = fmaf(a0, v.x, f0[0]); f0[1] = fmaf(a0, v.y, f0[1]);
        f0[2] = fmaf(a0, v.z, f0[2]); f0[3] = fmaf(a0, v.w, f0[3]);
        f1[0] = fmaf(a1, v.x, f1[0]); f1[1] = fmaf(a1, v.y, f1[1]);
        f1[2] = fmaf(a1, v.z, f1[2]); f1[3] = fmaf(a1, v.w, f1[3]);
    }
    float i0 = 1.0f / (s0 + 1e-16f), i1 = 1.0f / (s1 + 1e-16f);
    float4 o0, o1;
    o0.x = f0[0] * i0; o0.y = f0[1] * i0; o0.z = f0[2] * i0; o0.w = f0[3] * i0;
    o1.x = f1[0] * i1; o1.y = f1[1] * i1; o1.z = f1[2] * i1; o1.w = f1[3] * i1;
    float4* op = (float4*)(agg + (size_t)d * 256);
    op[lane] = o0;
    op[lane + 32] = o1;
}

// ---------------------------------------------------------------------------
// Attention logits for GAT2 (rows of xh2)
// ---------------------------------------------------------------------------
__global__ void att_kernel(const float* __restrict__ xh, const float* __restrict__ a_src,
                           const float* __restrict__ a_dst, float* __restrict__ out_s,
                           float* __restrict__ out_d, int rows, int heads, int ch) {
    int w = (blockIdx.x * blockDim.x + threadIdx.x) >> 5;
    int lane = threadIdx.x & 31;
    if (w >= rows) return;
    const float* row = xh + (size_t)w * ch;
    const float* as = a_src + (size_t)(w % heads) * ch;
    const float* ad = a_dst + (size_t)(w % heads) * ch;
    float ss = 0.0f, dd = 0.0f;
    for (int c = lane; c < ch; c += 32) {
        float v = row[c];
        ss += v * as[c];
        dd += v * ad[c];
    }
#pragma unroll
    for (int o = 16; o; o >>= 1) {
        ss += __shfl_down_sync(0xFFFFFFFFu, ss, o);
        dd += __shfl_down_sync(0xFFFFFFFFu, dd, o);
    }
    if (lane == 0) { out_s[w] = ss; out_d[w] = dd; }
}

// GAT head=1, ch=64; writes (agg + bias) * scale into out[d*ostride + ooff + c]
__global__ __launch_bounds__(256) void gat_pull_1_64(
        const int* __restrict__ rs, const int* __restrict__ csr,
        const float* __restrict__ as_, const float* __restrict__ ad_,
        const float* __restrict__ xh, const float* __restrict__ bias,
        const float* __restrict__ scale, float* __restrict__ out,
        int ostride, int ooff) {
    int d = (blockIdx.x * blockDim.x + threadIdx.x) >> 5;
    int lane = threadIdx.x & 31;
    if (d >= NN) return;
    int beg = rs[d], end = rs[d + 1];
    float add = ad_[d];
    float m = -INFINITY;
    for (int j = beg + lane; j < end; j += 32) {
        int s = __ldg(&csr[j]);
        float l = as_[s] + add; l = l > 0.f ? l : 0.2f * l;
        m = fmaxf(m, l);
    }
#pragma unroll
    for (int o = 16; o; o >>= 1) m = fmaxf(m, __shfl_xor_sync(0xFFFFFFFFu, m, o));
    float ssum = 0.f, f0 = 0.f, f1 = 0.f;
    for (int j = beg; j < end; ++j) {
        int s = __ldg(&csr[j]);
        float l = as_[s] + add; l = l > 0.f ? l : 0.2f * l;
        float a = __expf(l - m);
        ssum += a;
        float2 v = __ldg((const float2*)(xh + (size_t)s * 64) + lane);
        f0 = fmaf(a, v.x, f0); f1 = fmaf(a, v.y, f1);
    }
    float sc = scale[0];
    float inv = 1.0f / (ssum + 1e-16f);
    float2 o;
    o.x = (f0 * inv + bias[lane * 2 + 0]) * sc;
    o.y = (f1 * inv + bias[lane * 2 + 1]) * sc;
    ((float2*)(out + (size_t)d * ostride + ooff))[lane] = o;
}

// ---------------------------------------------------------------------------
// GCN pulls
// ---------------------------------------------------------------------------
__global__ __launch_bounds__(256) void gcn_pull_128(
        const int* __restrict__ rs, const int* __restrict__ csr,
        const float* __restrict__ dinv, const float* __restrict__ xw,
        const float* __restrict__ bias, float* __restrict__ out, int relu) {
    int d = (blockIdx.x * blockDim.x + threadIdx.x) >> 5;
    int lane = threadIdx.x & 31;
    if (d >= NN) return;
    int beg = rs[d], end = rs[d + 1];
    float dd = dinv[d];
    float f[4] = {0.f, 0.f, 0.f, 0.f};
    for (int j = beg; j < end; ++j) {
        int s = __ldg(&csr[j]);
        float nrm = __ldg(&dinv[s]) * dd;
        float4 v = __ldg((const float4*)(xw + (size_t)s * 128) + lane);
        f[0] = fmaf(nrm, v.x, f[0]); f[1] = fmaf(nrm, v.y, f[1]);
        f[2] = fmaf(nrm, v.z, f[2]); f[3] = fmaf(nrm, v.w, f[3]);
    }
    float4 bb = ((const float4*)bias)[lane];
    float4 o;
    o.x = f[0] + bb.x; o.y = f[1] + bb.y; o.z = f[2] + bb.z; o.w = f[3] + bb.w;
    if (relu) {
        o.x = fmaxf(o.x, 0.f); o.y = fmaxf(o.y, 0.f);
        o.z = fmaxf(o.z, 0.f); o.w = fmaxf(o.w, 0.f);
    }
    ((float4*)(out + (size_t)d * 128))[lane] = o;
}

__global__ __launch_bounds__(256) void gcn_pull_64(
        const int* __restrict__ rs, const int* __restrict__ csr,
        const float* __restrict__ dinv, const float* __restrict__ xw,
        const float* __restrict__ bias, const float* __restrict__ scale,
        float* __restrict__ out, int ostride, int ooff) {
    int d = (blockIdx.x * blockDim.x + threadIdx.x) >> 5;
    int lane = threadIdx.x & 31;
    if (d >= NN) return;
    int beg = rs[d], end = rs[d + 1];
    float dd = dinv[d];
    float f0 = 0.f, f1 = 0.f;
    for (int j = beg; j < end; ++j) {
        int s = __ldg(&csr[j]);
        float nrm = __ldg(&dinv[s]) * dd;
        float2 v = __ldg((const float2*)(xw + (size_t)s * 64) + lane);
        f0 = fmaf(nrm, v.x, f0); f1 = fmaf(nrm, v.y, f1);
    }
    float sc = scale[0];
    float2 o;
    o.x = (f0 + bias[lane * 2 + 0]) * sc;
    o.y = (f1 + bias[lane * 2 + 1]) * sc;
    ((float2*)(out + (size_t)d * ostride + ooff))[lane] = o;
}

// ---------------------------------------------------------------------------
static inline int cdiv(int a, int b) { return (a + b - 1) / b; }

extern "C" void kernel_launch(void* const* d_in, const int* in_sizes, int n_in,
                              void* d_out, int out_size) {
    const float* x      = (const float*)d_in[0];
    const int*   src    = (const int*)d_in[1];
    const int    E      = in_sizes[1] / 2;
    const int*   dst    = src + E;
    const float* gat1_W = (const float*)d_in[2];
    const float* att_s1 = (const float*)d_in[3];
    const float* att_d1 = (const float*)d_in[4];
    const float* gat1_b = (const float*)d_in[5];
    const float* gat2_W = (const float*)d_in[6];
    const float* att_s2 = (const float*)d_in[7];
    const float* att_d2 = (const float*)d_in[8];
    const float* gat2_b = (const float*)d_in[9];
    const float* gcn1_W = (const float*)d_in[10];
    const float* gcn1_b = (const float*)d_in[11];
    const float* gcn2_W = (const float*)d_in[12];
    const float* gcn2_b = (const float*)d_in[13];
    const float* lin1_W = (const float*)d_in[14];
    const float* lin1_b = (const float*)d_in[15];
    const float* lin2_W = (const float*)d_in[16];
    const float* lin2_b = (const float*)d_in[17];
    const float* lin3_W = (const float*)d_in[18];
    const float* lin3_b = (const float*)d_in[19];
    const float* wt     = (const float*)d_in[20];
    const float* wc     = (const float*)d_in[21];

    const int Etot = E + NN;

    float *agg1, *acc1, *as1, *ad1, *wa1s, *wa1d, *xh2, *as2, *ad2;
    float *xw1, *gcn1, *xw2, *dinv, *cat, *y1, *y2;
    int *counts, *rsp, *cursor, *csr;
    cudaGetSymbolAddress((void**)&agg1, g_agg1);
    cudaGetSymbolAddress((void**)&acc1, g_acc1);
    cudaGetSymbolAddress((void**)&as1, g_as1);
    cudaGetSymbolAddress((void**)&ad1, g_ad1);
    cudaGetSymbolAddress((void**)&wa1s, g_wa1s);
    cudaGetSymbolAddress((void**)&wa1d, g_wa1d);
    cudaGetSymbolAddress((void**)&xh2, g_xh2);
    cudaGetSymbolAddress((void**)&as2, g_as2);
    cudaGetSymbolAddress((void**)&ad2, g_ad2);
    cudaGetSymbolAddress((void**)&xw1, g_xw1);
    cudaGetSymbolAddress((void**)&gcn1, g_gcn1);
    cudaGetSymbolAddress((void**)&xw2, g_xw2);
    cudaGetSymbolAddress((void**)&dinv, g_dinv);
    cudaGetSymbolAddress((void**)&cat, g_cat);
    cudaGetSymbolAddress((void**)&y1, g_y1);
    cudaGetSymbolAddress((void**)&y2, g_y2);
    cudaGetSymbolAddress((void**)&counts, g_counts);
    cudaGetSymbolAddress((void**)&rsp, g_rs);
    cudaGetSymbolAddress((void**)&cursor, g_cursor);
    cudaGetSymbolAddress((void**)&csr, g_csr);

    static cudaStream_t s2 = nullptr, s3 = nullptr;
    static cudaEvent_t e0 = nullptr, eCSR = nullptr, eATT = nullptr, eGCN = nullptr;
    if (!s2) {
        cudaStreamCreateWithFlags(&s2, cudaStreamNonBlocking);
        cudaStreamCreateWithFlags(&s3, cudaStreamNonBlocking);
        cudaEventCreateWithFlags(&e0, cudaEventDisableTiming);
        cudaEventCreateWithFlags(&eCSR, cudaEventDisableTiming);
        cudaEventCreateWithFlags(&eATT, cudaEventDisableTiming);
        cudaEventCreateWithFlags(&eGCN, cudaEventDisableTiming);
    }

    const int TB = 256;
    const int GY = NN / 64;   // 625

    // ---- fork ----
    cudaEventRecord(e0, 0);
    cudaStreamWaitEvent(s2, e0, 0);
    cudaStreamWaitEvent(s3, e0, 0);

    // ---- origin: CSR build ----
    zero_int_kernel<<<cdiv(NN, TB), TB>>>(counts, NN);
    hist_kernel<<<cdiv(Etot, TB), TB>>>(dst, counts, E, Etot);
    scan_kernel<<<1, 1024>>>(counts, rsp, cursor, NN);
    csr_fill_kernel<<<cdiv(Etot, TB), TB>>>(src, dst, cursor, csr, E, Etot);
    dinv_kernel<<<cdiv(NN, TB), TB>>>(counts, dinv, NN);
    cudaEventRecord(eCSR, 0);

    // ---- s2: GAT1 logits straight from x ----
    wa_kernel<<<16, 256, 0, s2>>>(gat1_W, att_s1, att_d1, wa1s, wa1d);
    attx_kernel<<<cdiv(NN * 32, TB), TB, 0, s2>>>(x, wa1s, wa1d, as1, ad1);
    cudaEventRecord(eATT, s2);

    // ---- s3: GCN chain ----
    gemm_tf32_kernel<128><<<dim3(1, GY), 256, 0, s3>>>(x, gcn1_W, nullptr, xw1, 128, 128, 128, 128, 0);
    cudaStreamWaitEvent(s3, eCSR, 0);
    gcn_pull_128<<<cdiv(NN * 32, TB), TB, 0, s3>>>(rsp, csr, dinv, xw1, gcn1_b, gcn1, 1);
    gemm_tf32_kernel<64><<<dim3(1, GY), 256, 0, s3>>>(gcn1, gcn2_W, nullptr, xw2, 128, 128, 64, 64, 0);
    gcn_pull_64<<<cdiv(NN * 32, TB), TB, 0, s3>>>(rsp, csr, dinv, xw2, gcn2_b, wc, cat, 128, 0);
    cudaEventRecord(eGCN, s3);

    // ---- origin: GAT chain ----
    cudaStreamWaitEvent(0, eATT, 0);
    gat_pull_agg<<<cdiv(NN * 32, TB), TB>>>(rsp, csr, as1, ad1, x, agg1);
    // project per head: acc1[:, h*128:(h+1)*128] = ELU(agg_h @ W_h + b_h)
    gemm_tf32_kernel<128><<<dim3(1, GY), 256>>>(agg1, gat1_W, gat1_b, acc1,
                                                128, 256, 256, 256, 2);
    gemm_tf32_kernel<128><<<dim3(1, GY), 256>>>(agg1 + 128, gat1_W + 128, gat1_b + 128,
                                                acc1 + 128, 128, 256, 256, 256, 2);
    // GAT2
    gemm_tf32_kernel<64><<<dim3(1, GY), 256>>>(acc1, gat2_W, nullptr, xh2, 256, 256, 64, 64, 0);
    att_kernel<<<cdiv(NN * 32, TB), TB>>>(xh2, att_s2, att_d2, as2, ad2, NN, 1, 64);
    gat_pull_1_64<<<cdiv(NN * 32, TB), TB>>>(rsp, csr, as2, ad2, xh2, gat2_b, wt, cat, 128, 64);

    // ---- join + MLP head ----
    cudaStreamWaitEvent(0, eGCN, 0);
    gemm_tf32_kernel<128><<<dim3(2, GY), 256>>>(cat, lin1_W, lin1_b, y1, 128, 128, 256, 256, 0);
    gemm_tf32_kernel<128><<<dim3(1, GY), 256>>>(y1, lin2_W, lin2_b, y2, 256, 256, 128, 128, 0);
    gemm_tf32_kernel<64><<<dim3(1, GY), 256>>>(y2, lin3_W, lin3_b, (float*)d_out, 128, 128, 64, 64, 0);
}